// round 17
// baseline (speedup 1.0000x reference)
#include <cuda_runtime.h>
#include <cuda_bf16.h>
#include <cstdint>

// Problem dims
#define NV 64
#define NT 8192
#define NDA 256
#define NDS 256
#define NKR 8
#define NDU 64
#define NKA 40
#define M_TOTAL (NV * NT)  // 524288

// Output layout (float32, tuple flattened in reference-return order)
#define OFF_PDET 0
#define OFF_TAUX 1
#define OFF_YHAT 2
#define OFF_E    42
#define OFF_EV   (OFF_E + M_TOTAL)
#define OFF_RV   (OFF_EV + NV)
#define OFF_IV   (OFF_RV + NV)
#define OFF_ST   (OFF_IV + NV)
#define OFF_EN   (OFF_ST + M_TOTAL)
#define OFF_FLAG (OFF_EN + M_TOTAL)

// GEMM tiling: CTA = 64 rows x 256 cols, k-steps of 16
// 8 warps partitioned by N: warp w owns cols [w*32, w*32+32), all 64 rows.
#define BM 64
#define NKT 16                       // 256 / 16
#define GEMM_BLOCKS (M_TOTAL / BM)   // 8192
#define APACK_STRIDE 132             // uint2 per row (conflict-free-ish LDS.64)

// -------- device scratch --------
// B fragments: [kt(16)][term(2: hi,lo)][ntile(32)][lane(32)] as uint2 (256 KB, L2-resident)
__device__ uint2  g_Bf[NKT * 2 * 32 * 32];
__device__ float  g_zsn[NDS];
__device__ float  g_rview[NV];
__device__ double g_part[GEMM_BLOCKS];

// -------- helpers --------
__device__ __forceinline__ uint32_t pack_bf2(float a, float b) {
    __nv_bfloat162 h = __floats2bfloat162_rn(a, b);
    return *reinterpret_cast<uint32_t*>(&h);
}

#define MMA_BF16(cr, a, bx, by) \
    asm volatile( \
        "mma.sync.aligned.m16n8k16.row.col.f32.bf16.bf16.f32 " \
        "{%0,%1,%2,%3},{%4,%5,%6,%7},{%8,%9},{%0,%1,%2,%3};" \
        : "+f"((cr)[0]), "+f"((cr)[1]), "+f"((cr)[2]), "+f"((cr)[3]) \
        : "r"((a)[0]), "r"((a)[1]), "r"((a)[2]), "r"((a)[3]), "r"(bx), "r"(by))

// ============================================================
// Kernel P: build bf16 hi/lo B fragments in mma.sync per-lane layout
//   B[n][k] = Wwin[n*256 + k]; frag (kt, nt, lane):
//   n = nt*8 + lane/4, k0 = kt*16 + (lane%4)*2
//   reg.x = {B[k0], B[k0+1]}, reg.y = {B[k0+8], B[k0+9]}
// ============================================================
__global__ void k_prep_b(const float* __restrict__ W) {
    int t = blockIdx.x * 256 + threadIdx.x;   // 16384 total
    int kt = t >> 10, nt = (t >> 5) & 31, lane = t & 31;
    int n  = nt * 8 + (lane >> 2);
    int k0 = kt * 16 + (lane & 3) * 2;
    const float* row = W + n * NDA;
    float v0 = row[k0], v1 = row[k0 + 1], v2 = row[k0 + 8], v3 = row[k0 + 9];
    __nv_bfloat16 h0 = __float2bfloat16_rn(v0), h1 = __float2bfloat16_rn(v1);
    __nv_bfloat16 h2 = __float2bfloat16_rn(v2), h3 = __float2bfloat16_rn(v3);
    uint2 hv, lv;
    hv.x = ((uint32_t)__bfloat16_as_ushort(h1) << 16) | __bfloat16_as_ushort(h0);
    hv.y = ((uint32_t)__bfloat16_as_ushort(h3) << 16) | __bfloat16_as_ushort(h2);
    lv.x = pack_bf2(v0 - __bfloat162float(h0), v1 - __bfloat162float(h1));
    lv.y = pack_bf2(v2 - __bfloat162float(h2), v3 - __bfloat162float(h3));
    g_Bf[((kt * 2 + 0) * 32 + nt) * 32 + lane] = hv;
    g_Bf[((kt * 2 + 1) * 32 + nt) * 32 + lane] = lv;
}

// ============================================================
// Kernel A: scalars — zs, s, tau_x, p_det, y_hat, r_view, zsn
// ============================================================
__global__ void k_scalars(const float* __restrict__ alpha, const float* __restrict__ pi,
                          const float* __restrict__ US,
                          const float* __restrict__ Ws_w, const float* __restrict__ Ws_b,
                          const float* __restrict__ det_w, const float* __restrict__ det_b,
                          const float* __restrict__ cls_w, const float* __restrict__ cls_b,
                          const float* __restrict__ tau_c0, const float* __restrict__ lamU,
                          const float* __restrict__ lamC, const float* __restrict__ lamP,
                          const float* __restrict__ lamPi, const float* __restrict__ nu,
                          const float* __restrict__ risk, float* __restrict__ out) {
    __shared__ float us[NKR * NDU];
    __shared__ float zs[NDS];
    __shared__ float red[256];
    int t = threadIdx.x;
    us[t] = US[t];
    us[t + 256] = US[t + 256];
    __syncthreads();

    float z = Ws_b[t];
#pragma unroll 4
    for (int k = 0; k < NKR * NDU; k++) z += Ws_w[t * (NKR * NDU) + k] * us[k];
    zs[t] = z;
    __syncthreads();

    red[t] = z * z;
    __syncthreads();
    for (int s = 128; s > 0; s >>= 1) { if (t < s) red[t] += red[t + s]; __syncthreads(); }
    float ss = red[0];
    __syncthreads();

    red[t] = z * det_w[t];
    __syncthreads();
    for (int s = 128; s > 0; s >>= 1) { if (t < s) red[t] += red[t + s]; __syncthreads(); }
    float sdet = red[0] + det_b[0];
    __syncthreads();

    float norm = fmaxf(sqrtf(ss), 1e-12f);
    g_zsn[t] = zs[t] / norm;

    if (t < NKA) {
        float y = cls_b[t];
#pragma unroll 4
        for (int j = 0; j < NDS; j++) y += cls_w[t * NDS + j] * zs[j];
        out[OFF_YHAT + t] = 1.0f / (1.0f + expf(-y));
    }
    if (t < NV) {
        float r = -0.5f * alpha[t];
        g_rview[t] = r;
        out[OFF_RV + t] = r;
    }
    if (t == 0) {
        float ha = 0.0f;
        for (int i = 0; i < NV; i++) { float a = alpha[i]; ha += a * logf(a + 1e-8f); }
        float Ca = 1.0f - (-ha) / logf((float)NV);
        float hp = 0.0f;
        for (int i = 0; i < NKR; i++) { float p = pi[i]; hp += p * logf(p + 1e-8f); }
        float up = (-hp) / logf((float)NKR);
        float tx = tau_c0[0] - lamU[0] * nu[0] - lamC[0] * Ca + lamP[0] * risk[0] + lamPi[0] * up;
        out[OFF_TAUX] = tx;
        out[OFF_PDET] = 1.0f / (1.0f + expf(-(sdet - tx)));
    }
}

// ============================================================
// Kernel B: bf16 mma.sync GEMM (3-term hi/lo split) + fused row reduce -> e
//   Warps partitioned by N (disjoint B reads); B fragments register
//   double-buffered: kt+1's LDGs issue before kt's MMA body (hides L2 lat).
// ============================================================
struct __align__(16) SmemG {
    uint2 Apack[BM * APACK_STRIDE];    // {hi2, lo2} per k-pair, 67584 B
    float zsn[NDS];                    // 1 KB
    float2 red[BM][8];                 // (ssq, dot) per row per warp
    float esum[BM];
};

extern __shared__ char smem_raw[];

__global__ void __launch_bounds__(256, 2)
k_gemm_mma(const float* __restrict__ A, float* __restrict__ out) {
    SmemG& S = *reinterpret_cast<SmemG*>(smem_raw);
    const int tid  = threadIdx.x;
    const int wid  = tid >> 5;
    const int lane = tid & 31;
    const int m0   = blockIdx.x * BM;

    S.zsn[tid] = g_zsn[tid];

    // ---- load A rows, split to bf16 hi/lo, pack interleaved ----
    // thread: row r = tid>>2, k-pairs p = (tid&3) + 4*i, i = 0..31
    {
        int r = tid >> 2;
        int pbase = tid & 3;
        const float* arow = A + (size_t)(m0 + r) * NDA;
        uint2* ap = &S.Apack[r * APACK_STRIDE];
#pragma unroll
        for (int i = 0; i < 32; i++) {
            int p = pbase + 4 * i;
            float2 v = *reinterpret_cast<const float2*>(arow + 2 * p);
            __nv_bfloat16 h0 = __float2bfloat16_rn(v.x);
            __nv_bfloat16 h1 = __float2bfloat16_rn(v.y);
            uint2 w;
            w.x = ((uint32_t)__bfloat16_as_ushort(h1) << 16) |
                  __bfloat16_as_ushort(h0);
            w.y = pack_bf2(v.x - __bfloat162float(h0),
                           v.y - __bfloat162float(h1));
            ap[p] = w;
        }
    }
    __syncthreads();   // the only barrier before the epilogue

    float acc[4][4][4];   // [mtile][ntile][quad]
#pragma unroll
    for (int mt = 0; mt < 4; mt++)
#pragma unroll
        for (int nt = 0; nt < 4; nt++)
#pragma unroll
            for (int q = 0; q < 4; q++) acc[mt][nt][q] = 0.0f;

    const int rsub = lane >> 5 ? 0 : (lane >> 2);  // lane>>2 (0..7)
    const int koff = (lane & 3) * 2;

    // B fragment base pointers for this warp (disjoint across warps)
    const uint2* BhBase = &g_Bf[(0 * 32 + wid * 4) * 32 + lane];   // +kt*2048 per kt
    const uint2* BlBase = &g_Bf[(1 * 32 + wid * 4) * 32 + lane];

    // ---- prologue: load kt=0 B fragments into registers ----
    uint2 bh[4], bl[4];
#pragma unroll
    for (int nt = 0; nt < 4; nt++) {
        bh[nt] = BhBase[nt * 32];
        bl[nt] = BlBase[nt * 32];
    }

    for (int kt = 0; kt < NKT; kt++) {
        // ---- issue kt+1 B loads FIRST (hidden under the MMA body) ----
        uint2 nbh[4], nbl[4];
        if (kt + 1 < NKT) {
            const uint2* Bh = BhBase + (size_t)(kt + 1) * 2048;
            const uint2* Bl = BlBase + (size_t)(kt + 1) * 2048;
#pragma unroll
            for (int nt = 0; nt < 4; nt++) {
                nbh[nt] = Bh[nt * 32];
                nbl[nt] = Bl[nt * 32];
            }
        }
        // ---- MMA body for kt using prefetched bh/bl ----
        const int p0 = kt * 8 + (lane & 3);
#pragma unroll
        for (int mt = 0; mt < 4; mt++) {
            const uint2* ap_lo = &S.Apack[(mt * 16 + rsub) * APACK_STRIDE];
            const uint2* ap_hi = ap_lo + 8 * APACK_STRIDE;
            uint2 a00 = ap_lo[p0];
            uint2 a10 = ap_hi[p0];
            uint2 a01 = ap_lo[p0 + 4];
            uint2 a11 = ap_hi[p0 + 4];
            uint32_t ah[4] = { a00.x, a10.x, a01.x, a11.x };
            uint32_t al[4] = { a00.y, a10.y, a01.y, a11.y };
#pragma unroll
            for (int nt = 0; nt < 4; nt++) {
                float* cr = acc[mt][nt];
                MMA_BF16(cr, ah, bh[nt].x, bh[nt].y);   // Ah * Bh
                MMA_BF16(cr, al, bh[nt].x, bh[nt].y);   // Al * Bh
                MMA_BF16(cr, ah, bl[nt].x, bl[nt].y);   // Ah * Bl
            }
        }
        // ---- rotate buffers ----
        if (kt + 1 < NKT) {
#pragma unroll
            for (int nt = 0; nt < 4; nt++) {
                bh[nt] = nbh[nt];
                bl[nt] = nbl[nt];
            }
        }
    }

    // ---- epilogue: per-row sumsq & dot(zsn) over this warp's 32 cols ----
    // acc[mt][nt][0,1] -> row mt*16+rsub,   col wid*32 + nt*8 + koff + {0,1}
    // acc[mt][nt][2,3] -> row mt*16+rsub+8, same cols
#pragma unroll
    for (int mt = 0; mt < 4; mt++) {
        float ssq_lo = 0.f, dot_lo = 0.f, ssq_hi = 0.f, dot_hi = 0.f;
#pragma unroll
        for (int nt = 0; nt < 4; nt++) {
            int col = wid * 32 + nt * 8 + koff;
            float2 z = *reinterpret_cast<const float2*>(&S.zsn[col]);
            float* cr = acc[mt][nt];
            ssq_lo += cr[0] * cr[0] + cr[1] * cr[1];
            dot_lo += cr[0] * z.x + cr[1] * z.y;
            ssq_hi += cr[2] * cr[2] + cr[3] * cr[3];
            dot_hi += cr[2] * z.x + cr[3] * z.y;
        }
#pragma unroll
        for (int off = 1; off <= 2; off <<= 1) {
            ssq_lo += __shfl_xor_sync(0xFFFFFFFFu, ssq_lo, off);
            dot_lo += __shfl_xor_sync(0xFFFFFFFFu, dot_lo, off);
            ssq_hi += __shfl_xor_sync(0xFFFFFFFFu, ssq_hi, off);
            dot_hi += __shfl_xor_sync(0xFFFFFFFFu, dot_hi, off);
        }
        if ((lane & 3) == 0) {
            S.red[mt * 16 + rsub][wid]     = make_float2(ssq_lo, dot_lo);
            S.red[mt * 16 + rsub + 8][wid] = make_float2(ssq_hi, dot_hi);
        }
    }
    __syncthreads();
    if (tid < BM) {
        float ssq = 0.f, dot = 0.f;
#pragma unroll
        for (int w = 0; w < 8; w++) {
            float2 rd = S.red[tid][w];
            ssq += rd.x;
            dot += rd.y;
        }
        float e = dot / fmaxf(sqrtf(ssq), 1e-12f);
        out[OFF_E + m0 + tid] = e;
        S.esum[tid] = e;
    }
    __syncthreads();
    if (tid == 0) {
        double s = 0.0;
        for (int i = 0; i < BM; i++) s += (double)S.esum[i];
        g_part[blockIdx.x] = s;
    }
}

// ============================================================
// Kernel C: starts / ends from e
// ============================================================
__global__ void k_intervals(const float* __restrict__ out_ro, float* __restrict__ out) {
    int m = blockIdx.x * blockDim.x + threadIdx.x;
    if (m >= M_TOTAL) return;
    int v = m >> 13;
    int t = m & (NT - 1);
    float r = g_rview[v];
    const float* e = out_ro + OFF_E;
    bool I  = e[m] >= r;
    bool Ip = (t > 0)      ? (e[m - 1] >= r) : false;
    bool In = (t < NT - 1) ? (e[m + 1] >= r) : false;
    out[OFF_ST + m] = (I && !Ip) ? 1.0f : 0.0f;
    out[OFF_EN + m] = (I && !In) ? 1.0f : 0.0f;
}

// ============================================================
// Kernel D: E_view, I_view, flag_unknown
// ============================================================
__global__ void k_final(float* __restrict__ out) {
    int t = threadIdx.x;  // 64 threads
    double s = 0.0;
    const int per_view = NT / BM;  // 128
    for (int i = 0; i < per_view; i++) s += g_part[t * per_view + i];
    float ev = (float)(s / (double)NT);
    out[OFF_EV + t] = ev;
    bool iv = ev >= g_rview[t];
    out[OFF_IV + t] = iv ? 1.0f : 0.0f;
    int any = __syncthreads_or(iv ? 1 : 0);
    if (t == 0)
        out[OFF_FLAG] = ((out[OFF_PDET] >= 0.5f) && !any) ? 1.0f : 0.0f;
}

// ============================================================
extern "C" void kernel_launch(void* const* d_in, const int* in_sizes, int n_in,
                              void* d_out, int out_size) {
    const float* h      = (const float*)d_in[0];
    const float* alpha  = (const float*)d_in[1];
    const float* pi     = (const float*)d_in[2];
    const float* US     = (const float*)d_in[3];
    const float* Ws_w   = (const float*)d_in[6];
    const float* Ws_b   = (const float*)d_in[7];
    const float* det_w  = (const float*)d_in[8];
    const float* det_b  = (const float*)d_in[9];
    const float* cls_w  = (const float*)d_in[10];
    const float* cls_b  = (const float*)d_in[11];
    const float* Wwin   = (const float*)d_in[12];
    const float* tau_c0 = (const float*)d_in[13];
    const float* lamU   = (const float*)d_in[14];
    const float* lamC   = (const float*)d_in[15];
    const float* lamP   = (const float*)d_in[16];
    const float* lamPi  = (const float*)d_in[17];
    const float* nu     = (const float*)d_in[18];
    const float* risk   = (const float*)d_in[19];
    float* out = (float*)d_out;

    static bool attr_set = false;
    if (!attr_set) {
        cudaFuncSetAttribute(k_gemm_mma, cudaFuncAttributeMaxDynamicSharedMemorySize,
                             (int)sizeof(SmemG));
        attr_set = true;
    }

    k_prep_b<<<64, 256>>>(Wwin);
    k_scalars<<<1, 256>>>(alpha, pi, US, Ws_w, Ws_b, det_w, det_b, cls_w, cls_b,
                          tau_c0, lamU, lamC, lamP, lamPi, nu, risk, out);
    k_gemm_mma<<<GEMM_BLOCKS, 256, sizeof(SmemG)>>>(h, out);
    k_intervals<<<(M_TOTAL + 255) / 256, 256>>>(out, out);
    k_final<<<1, NV>>>(out);
}